// round 1
// baseline (speedup 1.0000x reference)
#include <cuda_runtime.h>

// Problem constants
#define BB   2
#define SS   2048
#define DD   1024
#define HH   16
#define DK   64
#define MTOK (BB*SS)          // 4096 rows
#define ELEMS (BB*SS*DD)      // 4,194,304 floats per tensor

// Scratch (module-load allocated, legal under the no-alloc rule)
__device__ float g_q[ELEMS];
__device__ float g_k[ELEMS];
__device__ float g_v[ELEMS];
__device__ float g_ctx[ELEMS];
__device__ float g_o[ELEMS];

// ---------------------------------------------------------------------------
// SGEMM: C[M,N] = A[M,K] * B[K,N] + bias[N] (+ res[M,N] if RES)
// 128x128 block tile, K-step 8, 256 threads, 8x8 per-thread microtile.
// M=4096, N=1024, K=1024 here; all dims divisible by tile sizes.
// ---------------------------------------------------------------------------
template <bool RES>
__global__ __launch_bounds__(256)
void sgemm128(const float* __restrict__ A, const float* __restrict__ Bm,
              const float* __restrict__ bias, const float* __restrict__ res,
              float* __restrict__ C, int M, int N, int K)
{
    __shared__ float As[8][128];
    __shared__ float Bs[8][128];

    const int tid  = threadIdx.x;
    const int brow = blockIdx.y * 128;
    const int bcol = blockIdx.x * 128;

    const int tx = tid & 15;          // 0..15
    const int ty = tid >> 4;          // 0..15
    const int row0 = ty * 8;
    const int col0 = tx * 8;

    // A loader: one float4 per thread: row = tid>>1 (0..127), colgrp = (tid&1)*4
    const int aRow = tid >> 1;
    const int aCol = (tid & 1) * 4;
    // B loader: row = tid>>5 (0..7), col = (tid&31)*4
    const int bRow = tid >> 5;
    const int bCol = (tid & 31) * 4;

    const float* Aptr = A + (size_t)(brow + aRow) * K + aCol;
    const float* Bptr = Bm + (size_t)bRow * N + bcol + bCol;

    float acc[8][8];
#pragma unroll
    for (int y = 0; y < 8; y++)
#pragma unroll
        for (int x = 0; x < 8; x++) acc[y][x] = 0.f;

    for (int k0 = 0; k0 < K; k0 += 8) {
        float4 a = *(const float4*)(Aptr + k0);
        float4 b = *(const float4*)(Bptr + (size_t)k0 * N);
        As[aCol + 0][aRow] = a.x;
        As[aCol + 1][aRow] = a.y;
        As[aCol + 2][aRow] = a.z;
        As[aCol + 3][aRow] = a.w;
        *(float4*)&Bs[bRow][bCol] = b;
        __syncthreads();

#pragma unroll
        for (int kk = 0; kk < 8; kk++) {
            float ar[8], br[8];
            *(float4*)&ar[0] = *(const float4*)&As[kk][row0];
            *(float4*)&ar[4] = *(const float4*)&As[kk][row0 + 4];
            *(float4*)&br[0] = *(const float4*)&Bs[kk][col0];
            *(float4*)&br[4] = *(const float4*)&Bs[kk][col0 + 4];
#pragma unroll
            for (int y = 0; y < 8; y++)
#pragma unroll
                for (int x = 0; x < 8; x++)
                    acc[y][x] = fmaf(ar[y], br[x], acc[y][x]);
        }
        __syncthreads();
    }

#pragma unroll
    for (int y = 0; y < 8; y++) {
        const int r = brow + row0 + y;
#pragma unroll
        for (int x4 = 0; x4 < 2; x4++) {
            const int c = bcol + col0 + x4 * 4;
            float4 bi = *(const float4*)&bias[c];
            float4 o;
            o.x = acc[y][x4 * 4 + 0] + bi.x;
            o.y = acc[y][x4 * 4 + 1] + bi.y;
            o.z = acc[y][x4 * 4 + 2] + bi.z;
            o.w = acc[y][x4 * 4 + 3] + bi.w;
            if (RES) {
                float4 rr = *(const float4*)&res[(size_t)r * N + c];
                o.x += rr.x; o.y += rr.y; o.z += rr.z; o.w += rr.w;
            }
            *(float4*)&C[(size_t)r * N + c] = o;
        }
    }
}

// ---------------------------------------------------------------------------
// Flash attention (causal), fp32.
// The reference's reshape (B,S,H*dk)->(B,H,S,dk) is a free reinterpretation of
// the flat buffer: element (b,h,s,d) lives at b*H*S*DK + h*S*DK + s*DK + d.
// Block = one (b, h, 64-query tile). 64 threads; thread i owns query row i.
// K/V 64x64 tiles staged in smem; per-thread registers hold q[64], acc[64],
// and 32 scores at a time (chunked online softmax keeps regs < 200).
// ---------------------------------------------------------------------------
__global__ __launch_bounds__(64)
void flash_kernel(const float* __restrict__ Q, const float* __restrict__ Kg,
                  const float* __restrict__ Vg, float* __restrict__ O)
{
    const int qt = blockIdx.x;          // 0..31 query tile
    const int h  = blockIdx.y;
    const int b  = blockIdx.z;
    const int i  = threadIdx.x;         // 0..63

    const size_t base = ((size_t)(b * HH + h)) * SS * DK;
    const float* Kb = Kg + base;
    const float* Vb = Vg + base;

    __shared__ float Ks[64 * 64];
    __shared__ float Vs[64 * 64];

    const int qrow = qt * 64 + i;

    float q[64];
    {
        const float4* qp = (const float4*)(Q + base + (size_t)qrow * DK);
#pragma unroll
        for (int d4 = 0; d4 < 16; d4++) {
            float4 t = qp[d4];
            q[4 * d4 + 0] = t.x * 0.125f;   // 1/sqrt(64)
            q[4 * d4 + 1] = t.y * 0.125f;
            q[4 * d4 + 2] = t.z * 0.125f;
            q[4 * d4 + 3] = t.w * 0.125f;
        }
    }

    float acc[64];
#pragma unroll
    for (int d = 0; d < 64; d++) acc[d] = 0.f;
    float m = -1e30f, l = 0.f;

    for (int kt = 0; kt <= qt; kt++) {
        // cooperative tile load: 1024 float4s each for K and V, coalesced
        const float4* Kp = (const float4*)(Kb + (size_t)kt * 64 * DK);
        const float4* Vp = (const float4*)(Vb + (size_t)kt * 64 * DK);
        float4* Ksp = (float4*)Ks;
        float4* Vsp = (float4*)Vs;
#pragma unroll
        for (int n = 0; n < 16; n++) {
            int t = n * 64 + i;
            Ksp[t] = Kp[t];
            Vsp[t] = Vp[t];
        }
        __syncthreads();

        const bool diag = (kt == qt);

#pragma unroll 1
        for (int jh = 0; jh < 64; jh += 32) {
            float sreg[32];
            float tmax = -1e30f;
#pragma unroll
            for (int jj = 0; jj < 32; jj++) {
                const int j = jh + jj;
                const float4* kr = (const float4*)(Ks + j * 64);
                float s0 = 0.f, s1 = 0.f, s2 = 0.f, s3 = 0.f;
#pragma unroll
                for (int d4 = 0; d4 < 16; d4++) {
                    float4 kv = kr[d4];
                    s0 = fmaf(q[4 * d4 + 0], kv.x, s0);
                    s1 = fmaf(q[4 * d4 + 1], kv.y, s1);
                    s2 = fmaf(q[4 * d4 + 2], kv.z, s2);
                    s3 = fmaf(q[4 * d4 + 3], kv.w, s3);
                }
                float s = (s0 + s1) + (s2 + s3);
                if (diag && j > i) s = -1e30f;   // causal mask
                sreg[jj] = s;
                tmax = fmaxf(tmax, s);
            }
            const float mn   = fmaxf(m, tmax);
            const float corr = __expf(m - mn);
            l *= corr;
#pragma unroll
            for (int d = 0; d < 64; d++) acc[d] *= corr;
            m = mn;
#pragma unroll
            for (int jj = 0; jj < 32; jj++) {
                const int j = jh + jj;
                const float p = __expf(sreg[jj] - m);
                l += p;
                const float4* vr = (const float4*)(Vs + j * 64);
#pragma unroll
                for (int d4 = 0; d4 < 16; d4++) {
                    float4 vv = vr[d4];
                    acc[4 * d4 + 0] = fmaf(p, vv.x, acc[4 * d4 + 0]);
                    acc[4 * d4 + 1] = fmaf(p, vv.y, acc[4 * d4 + 1]);
                    acc[4 * d4 + 2] = fmaf(p, vv.z, acc[4 * d4 + 2]);
                    acc[4 * d4 + 3] = fmaf(p, vv.w, acc[4 * d4 + 3]);
                }
            }
        }
        __syncthreads();
    }

    const float inv = 1.0f / l;
    float4* op = (float4*)(O + base + (size_t)qrow * DK);
#pragma unroll
    for (int d4 = 0; d4 < 16; d4++) {
        float4 t;
        t.x = acc[4 * d4 + 0] * inv;
        t.y = acc[4 * d4 + 1] * inv;
        t.z = acc[4 * d4 + 2] * inv;
        t.w = acc[4 * d4 + 3] * inv;
        op[d4] = t;
    }
}

// ---------------------------------------------------------------------------
// LayerNorm over rows of 1024. One block (256 threads) per row, float4 I/O.
// ---------------------------------------------------------------------------
__global__ __launch_bounds__(256)
void ln_kernel(const float* __restrict__ in, const float* __restrict__ gamma,
               const float* __restrict__ beta, float* __restrict__ out)
{
    const int row = blockIdx.x;
    const int t   = threadIdx.x;       // 256 threads * float4 = 1024
    const float4* r = (const float4*)(in + (size_t)row * DD);
    float4 v = r[t];

    float s  = v.x + v.y + v.z + v.w;
    float s2 = v.x * v.x + v.y * v.y + v.z * v.z + v.w * v.w;

#pragma unroll
    for (int off = 16; off > 0; off >>= 1) {
        s  += __shfl_xor_sync(0xffffffffu, s,  off);
        s2 += __shfl_xor_sync(0xffffffffu, s2, off);
    }
    __shared__ float sm[8], sm2[8];
    const int warp = t >> 5, lane = t & 31;
    if (lane == 0) { sm[warp] = s; sm2[warp] = s2; }
    __syncthreads();
    float tot = 0.f, tot2 = 0.f;
#pragma unroll
    for (int w = 0; w < 8; w++) { tot += sm[w]; tot2 += sm2[w]; }

    const float mean = tot * (1.0f / DD);
    const float var  = tot2 * (1.0f / DD) - mean * mean;
    const float rstd = rsqrtf(var + 1e-5f);

    float4 g  = ((const float4*)gamma)[t];
    float4 be = ((const float4*)beta)[t];
    float4 o;
    o.x = (v.x - mean) * rstd * g.x + be.x;
    o.y = (v.y - mean) * rstd * g.y + be.y;
    o.z = (v.z - mean) * rstd * g.z + be.z;
    o.w = (v.w - mean) * rstd * g.w + be.w;
    ((float4*)(out + (size_t)row * DD))[t] = o;
}

// ---------------------------------------------------------------------------
extern "C" void kernel_launch(void* const* d_in, const int* in_sizes, int n_in,
                              void* d_out, int out_size)
{
    const float* x     = (const float*)d_in[0];
    const float* Wk    = (const float*)d_in[1];
    const float* bk    = (const float*)d_in[2];
    const float* Wq    = (const float*)d_in[3];
    const float* bq    = (const float*)d_in[4];
    const float* Wv    = (const float*)d_in[5];
    const float* bv    = (const float*)d_in[6];
    const float* Wo    = (const float*)d_in[7];
    const float* bo    = (const float*)d_in[8];
    const float* gamma = (const float*)d_in[9];
    const float* beta  = (const float*)d_in[10];
    float* out = (float*)d_out;

    float *q, *k, *v, *ctx, *o;
    cudaGetSymbolAddress((void**)&q,   g_q);
    cudaGetSymbolAddress((void**)&k,   g_k);
    cudaGetSymbolAddress((void**)&v,   g_v);
    cudaGetSymbolAddress((void**)&ctx, g_ctx);
    cudaGetSymbolAddress((void**)&o,   g_o);

    dim3 gg(DD / 128, MTOK / 128);   // (8, 32)

    sgemm128<false><<<gg, 256>>>(x, Wq, bq, nullptr, q, MTOK, DD, DD);
    sgemm128<false><<<gg, 256>>>(x, Wk, bk, nullptr, k, MTOK, DD, DD);
    sgemm128<false><<<gg, 256>>>(x, Wv, bv, nullptr, v, MTOK, DD, DD);

    flash_kernel<<<dim3(SS / 64, HH, BB), 64>>>(q, k, v, ctx);

    sgemm128<true><<<gg, 256>>>(ctx, Wo, bo, x, o, MTOK, DD, DD);

    ln_kernel<<<MTOK, 256>>>(o, gamma, beta, out);
}

// round 2
// speedup vs baseline: 4.0148x; 4.0148x over previous
#include <cuda_runtime.h>
#include <cstdint>

#define BB   2
#define SS   2048
#define DD   1024
#define HH   16
#define DKH  64
#define MTOK (BB*SS)
#define ELEMS (BB*SS*DD)

__device__ float g_q[ELEMS];
__device__ float g_k[ELEMS];
__device__ float g_v[ELEMS];
__device__ float g_ctx[ELEMS];
__device__ float g_o[ELEMS];

// ---------------------------------------------------------------------------
// tf32 helpers
// ---------------------------------------------------------------------------
__device__ __forceinline__ unsigned f2tf(float x) {
    unsigned u;
    asm("cvt.rna.tf32.f32 %0, %1;" : "=r"(u) : "f"(x));
    return u;
}
__device__ __forceinline__ float f2tff(float x) {
    return __uint_as_float(f2tf(x));
}
__device__ __forceinline__ void mma_tf32(float c[4], const unsigned a[4], const unsigned b[2]) {
    asm volatile(
        "mma.sync.aligned.m16n8k8.row.col.f32.tf32.tf32.f32 "
        "{%0,%1,%2,%3}, {%4,%5,%6,%7}, {%8,%9}, {%0,%1,%2,%3};\n"
        : "+f"(c[0]), "+f"(c[1]), "+f"(c[2]), "+f"(c[3])
        : "r"(a[0]), "r"(a[1]), "r"(a[2]), "r"(a[3]), "r"(b[0]), "r"(b[1]));
}

// ---------------------------------------------------------------------------
// tf32 tensor-core GEMM: C[M,N] = A[M,K] @ B[K,N] + bias (+ res)
// Block 128x128, K-step 32, 256 threads (8 warps as 4x2), warp tile 32x64.
// smem XOR-swizzled for conflict-free fragment loads.
// ---------------------------------------------------------------------------
template <bool RES>
__global__ __launch_bounds__(256, 2)
void gemm_tf32(const float* __restrict__ A, const float* __restrict__ Bm,
               const float* __restrict__ bias, const float* __restrict__ res,
               float* __restrict__ C, int M, int N, int K)
{
    __shared__ float As[128 * 32];   // (m,k) at As[m*32 + (k ^ 4*(m&7))]
    __shared__ float Bs[32 * 128];   // (k,n) at Bs[k*128 + (n&96) | ((n&31)^(8*(k&3)))]

    const int tid   = threadIdx.x;
    const int lane  = tid & 31;
    const int warp  = tid >> 5;
    const int g     = lane >> 2;     // group id (0..7)
    const int tg    = lane & 3;      // thread-in-group (0..3)
    const int warpM = warp & 3;
    const int warpN = warp >> 2;
    const int brow  = blockIdx.y * 128;
    const int bcol  = blockIdx.x * 128;

    float acc[2][8][4];
#pragma unroll
    for (int mt = 0; mt < 2; mt++)
#pragma unroll
        for (int nt = 0; nt < 8; nt++)
#pragma unroll
            for (int e = 0; e < 4; e++) acc[mt][nt][e] = 0.f;

    for (int kt = 0; kt < K; kt += 32) {
        // load A tile 128x32
#pragma unroll
        for (int i = 0; i < 4; i++) {
            int lin = i * 256 + tid;
            int m = lin >> 3, kg = lin & 7;
            float4 a = *(const float4*)(A + (size_t)(brow + m) * K + kt + kg * 4);
            float4 t;
            t.x = f2tff(a.x); t.y = f2tff(a.y); t.z = f2tff(a.z); t.w = f2tff(a.w);
            ((float4*)(As + m * 32))[kg ^ (m & 7)] = t;
        }
        // load B tile 32x128
#pragma unroll
        for (int i = 0; i < 4; i++) {
            int lin = i * 256 + tid;
            int k = lin >> 5, ng = lin & 31;
            float4 b = *(const float4*)(Bm + (size_t)(kt + k) * N + bcol + ng * 4);
            float4 t;
            t.x = f2tff(b.x); t.y = f2tff(b.y); t.z = f2tff(b.z); t.w = f2tff(b.w);
            ((float4*)(Bs + k * 128))[(ng & 24) | ((ng & 7) ^ (2 * (k & 3)))] = t;
        }
        __syncthreads();

#pragma unroll
        for (int k8 = 0; k8 < 4; k8++) {
            const int kk = k8 * 8 + tg;
            unsigned af[2][4], bf[8][2];
#pragma unroll
            for (int mt = 0; mt < 2; mt++) {
                const int r = warpM * 32 + mt * 16 + g;
                const float* r0 = As + r * 32;
                const float* r1 = As + (r + 8) * 32;
                const int s = 4 * g;               // (r&7) == g
                af[mt][0] = __float_as_uint(r0[kk ^ s]);
                af[mt][1] = __float_as_uint(r1[kk ^ s]);
                af[mt][2] = __float_as_uint(r0[(kk + 4) ^ s]);
                af[mt][3] = __float_as_uint(r1[(kk + 4) ^ s]);
            }
#pragma unroll
            for (int nt = 0; nt < 8; nt++) {
                const int c = warpN * 64 + nt * 8 + g;
                const int cs = (c & 96) | ((c & 31) ^ (8 * tg));
                bf[nt][0] = __float_as_uint(Bs[kk * 128 + cs]);
                bf[nt][1] = __float_as_uint(Bs[(kk + 4) * 128 + cs]);
            }
#pragma unroll
            for (int mt = 0; mt < 2; mt++)
#pragma unroll
                for (int nt = 0; nt < 8; nt++)
                    mma_tf32(acc[mt][nt], af[mt], bf[nt]);
        }
        __syncthreads();
    }

    // epilogue
#pragma unroll
    for (int mt = 0; mt < 2; mt++) {
        const int r0 = brow + warpM * 32 + mt * 16 + g;
#pragma unroll
        for (int nt = 0; nt < 8; nt++) {
            const int c = bcol + warpN * 64 + nt * 8 + 2 * tg;
            float2 bi = *(const float2*)(bias + c);
            float2 o0, o1;
            o0.x = acc[mt][nt][0] + bi.x;  o0.y = acc[mt][nt][1] + bi.y;
            o1.x = acc[mt][nt][2] + bi.x;  o1.y = acc[mt][nt][3] + bi.y;
            if (RES) {
                float2 ra = *(const float2*)(res + (size_t)r0 * N + c);
                float2 rb = *(const float2*)(res + (size_t)(r0 + 8) * N + c);
                o0.x += ra.x; o0.y += ra.y;
                o1.x += rb.x; o1.y += rb.y;
            }
            *(float2*)(C + (size_t)r0 * N + c)       = o0;
            *(float2*)(C + (size_t)(r0 + 8) * N + c) = o1;
        }
    }
}

// ---------------------------------------------------------------------------
// Flash attention (causal), tf32 tensor cores.
// Block = (b, h, 64-query tile), 128 threads = 4 warps, warp owns 16 q-rows.
// Q fragments resident in registers; K/V tiles + P matrix staged in swizzled
// smem. Online softmax on mma accumulator fragments.
// ---------------------------------------------------------------------------
__global__ __launch_bounds__(128, 3)
void flash_tc(const float* __restrict__ Q, const float* __restrict__ Kg,
              const float* __restrict__ Vg, float* __restrict__ O)
{
    __shared__ float Ks[64 * 64];  // (j,d) at Ks[j*64 + (d ^ 4*(j&7))]
    __shared__ float Vs[64 * 64];  // (j,d) at Vs[j*64 + (d ^ 8*(j&3))]
    __shared__ float Ps[64 * 64];  // (r,k) at Ps[r*64 + (k ^ 4*(r&7))]

    const int qt   = (int)gridDim.x - 1 - (int)blockIdx.x;  // big tiles first
    const int h    = blockIdx.y, b = blockIdx.z;
    const int tid  = threadIdx.x;
    const int w    = tid >> 5;
    const int lane = tid & 31;
    const int g    = lane >> 2;
    const int tg   = lane & 3;
    const size_t base = ((size_t)(b * HH + h)) * SS * DKH;

    // ---- stage Q (scaled by 1/sqrt(dk)=0.125, tf32) into Ks, pull fragments ----
#pragma unroll
    for (int i = 0; i < 8; i++) {
        int lin = i * 128 + tid;
        int r = lin >> 4, dg = lin & 15;
        float4 q = *(const float4*)(Q + base + (size_t)(qt * 64 + r) * DKH + dg * 4);
        float4 t;
        t.x = f2tff(q.x * 0.125f); t.y = f2tff(q.y * 0.125f);
        t.z = f2tff(q.z * 0.125f); t.w = f2tff(q.w * 0.125f);
        ((float4*)(Ks + r * 64))[dg ^ (r & 7)] = t;
    }
    __syncthreads();

    unsigned qf[8][4];
    const int r0l = w * 16 + g;          // local q row (0..63), (r0l&7)==g
    const int sw  = 4 * g;
    {
        const float* p0 = Ks + r0l * 64;
        const float* p1 = Ks + (r0l + 8) * 64;
#pragma unroll
        for (int k8 = 0; k8 < 8; k8++) {
            const int kk = k8 * 8 + tg;
            qf[k8][0] = __float_as_uint(p0[kk ^ sw]);
            qf[k8][1] = __float_as_uint(p1[kk ^ sw]);
            qf[k8][2] = __float_as_uint(p0[(kk + 4) ^ sw]);
            qf[k8][3] = __float_as_uint(p1[(kk + 4) ^ sw]);
        }
    }
    __syncthreads();

    float oacc[8][4];
#pragma unroll
    for (int nt = 0; nt < 8; nt++)
#pragma unroll
        for (int e = 0; e < 4; e++) oacc[nt][e] = 0.f;
    float m0 = -1e30f, m1 = -1e30f, l0 = 0.f, l1 = 0.f;

    for (int kt = 0; kt <= qt; kt++) {
        // ---- load K and V tiles (coalesced, swizzled, tf32) ----
#pragma unroll
        for (int i = 0; i < 8; i++) {
            int lin = i * 128 + tid;
            int j = lin >> 4, dg = lin & 15;
            const size_t go = base + (size_t)(kt * 64 + j) * DKH + dg * 4;
            float4 kv = *(const float4*)(Kg + go);
            float4 vv = *(const float4*)(Vg + go);
            float4 tk, tv;
            tk.x = f2tff(kv.x); tk.y = f2tff(kv.y); tk.z = f2tff(kv.z); tk.w = f2tff(kv.w);
            tv.x = f2tff(vv.x); tv.y = f2tff(vv.y); tv.z = f2tff(vv.z); tv.w = f2tff(vv.w);
            ((float4*)(Ks + j * 64))[dg ^ (j & 7)]       = tk;
            ((float4*)(Vs + j * 64))[dg ^ (2 * (j & 3))] = tv;
        }
        __syncthreads();

        // ---- S = Q @ K^T ----
        float sacc[8][4];
#pragma unroll
        for (int nt = 0; nt < 8; nt++)
#pragma unroll
            for (int e = 0; e < 4; e++) sacc[nt][e] = 0.f;

#pragma unroll
        for (int k8 = 0; k8 < 8; k8++) {
            const int kk = k8 * 8 + tg;
#pragma unroll
            for (int nt = 0; nt < 8; nt++) {
                const int j = nt * 8 + g;          // (j&7)==g
                unsigned bf[2];
                bf[0] = __float_as_uint(Ks[j * 64 + (kk ^ (4 * g))]);
                bf[1] = __float_as_uint(Ks[j * 64 + ((kk + 4) ^ (4 * g))]);
                mma_tf32(sacc[nt], qf[k8], bf);
            }
        }

        // ---- causal mask (diagonal tile only) ----
        if (kt == qt) {
#pragma unroll
            for (int nt = 0; nt < 8; nt++) {
                const int c = nt * 8 + 2 * tg;
                if (c     > r0l)     sacc[nt][0] = -1e30f;
                if (c + 1 > r0l)     sacc[nt][1] = -1e30f;
                if (c     > r0l + 8) sacc[nt][2] = -1e30f;
                if (c + 1 > r0l + 8) sacc[nt][3] = -1e30f;
            }
        }

        // ---- online softmax ----
        float t0 = -1e30f, t1 = -1e30f;
#pragma unroll
        for (int nt = 0; nt < 8; nt++) {
            t0 = fmaxf(t0, fmaxf(sacc[nt][0], sacc[nt][1]));
            t1 = fmaxf(t1, fmaxf(sacc[nt][2], sacc[nt][3]));
        }
        t0 = fmaxf(t0, __shfl_xor_sync(0xffffffffu, t0, 1));
        t0 = fmaxf(t0, __shfl_xor_sync(0xffffffffu, t0, 2));
        t1 = fmaxf(t1, __shfl_xor_sync(0xffffffffu, t1, 1));
        t1 = fmaxf(t1, __shfl_xor_sync(0xffffffffu, t1, 2));

        const float mn0 = fmaxf(m0, t0);
        const float mn1 = fmaxf(m1, t1);
        const float c0 = __expf(m0 - mn0);
        const float c1 = __expf(m1 - mn1);
        m0 = mn0; m1 = mn1;
        l0 *= c0;  l1 *= c1;
#pragma unroll
        for (int nt = 0; nt < 8; nt++) {
            oacc[nt][0] *= c0; oacc[nt][1] *= c0;
            oacc[nt][2] *= c1; oacc[nt][3] *= c1;
        }
        float s0 = 0.f, s1 = 0.f;
#pragma unroll
        for (int nt = 0; nt < 8; nt++) {
            sacc[nt][0] = __expf(sacc[nt][0] - m0);
            sacc[nt][1] = __expf(sacc[nt][1] - m0);
            sacc[nt][2] = __expf(sacc[nt][2] - m1);
            sacc[nt][3] = __expf(sacc[nt][3] - m1);
            s0 += sacc[nt][0] + sacc[nt][1];
            s1 += sacc[nt][2] + sacc[nt][3];
        }
        s0 += __shfl_xor_sync(0xffffffffu, s0, 1);
        s0 += __shfl_xor_sync(0xffffffffu, s0, 2);
        s1 += __shfl_xor_sync(0xffffffffu, s1, 1);
        s1 += __shfl_xor_sync(0xffffffffu, s1, 2);
        l0 += s0; l1 += s1;

        // ---- write P to smem (A-fragment swizzle), warp-private rows ----
#pragma unroll
        for (int nt = 0; nt < 8; nt++) {
            const int c = (nt * 8 + 2 * tg) ^ sw;   // XOR(mult of 4) keeps pair contiguous
            float2 pa, pb;
            pa.x = f2tff(sacc[nt][0]); pa.y = f2tff(sacc[nt][1]);
            pb.x = f2tff(sacc[nt][2]); pb.y = f2tff(sacc[nt][3]);
            *(float2*)(Ps + r0l * 64 + c)       = pa;
            *(float2*)(Ps + (r0l + 8) * 64 + c) = pb;
        }
        __syncwarp();

        // ---- O += P @ V ----
#pragma unroll
        for (int k8 = 0; k8 < 8; k8++) {
            const int kk = k8 * 8 + tg;
            unsigned pa[4];
            const float* pr0 = Ps + r0l * 64;
            const float* pr1 = Ps + (r0l + 8) * 64;
            pa[0] = __float_as_uint(pr0[kk ^ sw]);
            pa[1] = __float_as_uint(pr1[kk ^ sw]);
            pa[2] = __float_as_uint(pr0[(kk + 4) ^ sw]);
            pa[3] = __float_as_uint(pr1[(kk + 4) ^ sw]);
#pragma unroll
            for (int nt = 0; nt < 8; nt++) {
                const int d = nt * 8 + g;
                unsigned bf[2];
                bf[0] = __float_as_uint(Vs[kk * 64 + (d ^ (8 * tg))]);
                bf[1] = __float_as_uint(Vs[(kk + 4) * 64 + (d ^ (8 * tg))]);
                mma_tf32(oacc[nt], pa, bf);
            }
        }
        __syncthreads();
    }

    // ---- epilogue ----
    const float i0 = 1.0f / l0;
    const float i1 = 1.0f / l1;
    const int rg = qt * 64 + r0l;
#pragma unroll
    for (int nt = 0; nt < 8; nt++) {
        const int c = nt * 8 + 2 * tg;
        float2 o0, o1;
        o0.x = oacc[nt][0] * i0; o0.y = oacc[nt][1] * i0;
        o1.x = oacc[nt][2] * i1; o1.y = oacc[nt][3] * i1;
        *(float2*)(O + base + (size_t)rg * DKH + c)       = o0;
        *(float2*)(O + base + (size_t)(rg + 8) * DKH + c) = o1;
    }
}

// ---------------------------------------------------------------------------
// LayerNorm over rows of 1024.
// ---------------------------------------------------------------------------
__global__ __launch_bounds__(256)
void ln_kernel(const float* __restrict__ in, const float* __restrict__ gamma,
               const float* __restrict__ beta, float* __restrict__ out)
{
    const int row = blockIdx.x;
    const int t   = threadIdx.x;
    const float4* r = (const float4*)(in + (size_t)row * DD);
    float4 v = r[t];

    float s  = v.x + v.y + v.z + v.w;
    float s2 = v.x * v.x + v.y * v.y + v.z * v.z + v.w * v.w;

#pragma unroll
    for (int off = 16; off > 0; off >>= 1) {
        s  += __shfl_xor_sync(0xffffffffu, s,  off);
        s2 += __shfl_xor_sync(0xffffffffu, s2, off);
    }
    __shared__ float sm[8], sm2[8];
    const int warp = t >> 5, lane = t & 31;
    if (lane == 0) { sm[warp] = s; sm2[warp] = s2; }
    __syncthreads();
    float tot = 0.f, tot2 = 0.f;
#pragma unroll
    for (int w = 0; w < 8; w++) { tot += sm[w]; tot2 += sm2[w]; }

    const float mean = tot * (1.0f / DD);
    const float var  = tot2 * (1.0f / DD) - mean * mean;
    const float rstd = rsqrtf(var + 1e-5f);

    float4 g  = ((const float4*)gamma)[t];
    float4 be = ((const float4*)beta)[t];
    float4 o;
    o.x = (v.x - mean) * rstd * g.x + be.x;
    o.y = (v.y - mean) * rstd * g.y + be.y;
    o.z = (v.z - mean) * rstd * g.z + be.z;
    o.w = (v.w - mean) * rstd * g.w + be.w;
    ((float4*)(out + (size_t)row * DD))[t] = o;
}

// ---------------------------------------------------------------------------
extern "C" void kernel_launch(void* const* d_in, const int* in_sizes, int n_in,
                              void* d_out, int out_size)
{
    const float* x     = (const float*)d_in[0];
    const float* Wk    = (const float*)d_in[1];
    const float* bk    = (const float*)d_in[2];
    const float* Wq    = (const float*)d_in[3];
    const float* bq    = (const float*)d_in[4];
    const float* Wv    = (const float*)d_in[5];
    const float* bv    = (const float*)d_in[6];
    const float* Wo    = (const float*)d_in[7];
    const float* bo    = (const float*)d_in[8];
    const float* gamma = (const float*)d_in[9];
    const float* beta  = (const float*)d_in[10];
    float* out = (float*)d_out;

    float *q, *k, *v, *ctx, *o;
    cudaGetSymbolAddress((void**)&q,   g_q);
    cudaGetSymbolAddress((void**)&k,   g_k);
    cudaGetSymbolAddress((void**)&v,   g_v);
    cudaGetSymbolAddress((void**)&ctx, g_ctx);
    cudaGetSymbolAddress((void**)&o,   g_o);

    dim3 gg(DD / 128, MTOK / 128);   // (8, 32)

    gemm_tf32<false><<<gg, 256>>>(x, Wq, bq, nullptr, q, MTOK, DD, DD);
    gemm_tf32<false><<<gg, 256>>>(x, Wk, bk, nullptr, k, MTOK, DD, DD);
    gemm_tf32<false><<<gg, 256>>>(x, Wv, bv, nullptr, v, MTOK, DD, DD);

    flash_tc<<<dim3(SS / 64, HH, BB), 128>>>(q, k, v, ctx);

    gemm_tf32<true><<<gg, 256>>>(ctx, Wo, bo, x, o, MTOK, DD, DD);

    ln_kernel<<<MTOK, 256>>>(o, gamma, beta, out);
}

// round 3
// speedup vs baseline: 4.7431x; 1.1814x over previous
#include <cuda_runtime.h>
#include <cstdint>

#define BB   2
#define SS   2048
#define DD   1024
#define HH   16
#define DKH  64
#define MTOK (BB*SS)
#define ELEMS (BB*SS*DD)

__device__ float g_q[ELEMS];
__device__ float g_k[ELEMS];
__device__ float g_v[ELEMS];
__device__ float g_ctx[ELEMS];
__device__ float g_o[ELEMS];

// ---------------------------------------------------------------------------
// mma + cp.async helpers. tf32 operands are raw f32 bits (HW ignores the low
// 13 mantissa bits -> truncation rounding; cutlass tfloat32_t does the same).
// ---------------------------------------------------------------------------
__device__ __forceinline__ void mma_tf32(float c[4], const unsigned a[4], const unsigned b[2]) {
    asm volatile(
        "mma.sync.aligned.m16n8k8.row.col.f32.tf32.tf32.f32 "
        "{%0,%1,%2,%3}, {%4,%5,%6,%7}, {%8,%9}, {%0,%1,%2,%3};\n"
        : "+f"(c[0]), "+f"(c[1]), "+f"(c[2]), "+f"(c[3])
        : "r"(a[0]), "r"(a[1]), "r"(a[2]), "r"(a[3]), "r"(b[0]), "r"(b[1]));
}
__device__ __forceinline__ unsigned su(const void* p) {
    return (unsigned)__cvta_generic_to_shared(p);
}
#define CPA(dst, src) asm volatile("cp.async.ca.shared.global [%0], [%1], 16;\n" :: "r"(dst), "l"(src))
#define CPC() asm volatile("cp.async.commit_group;\n")
#define CPW(n) asm volatile("cp.async.wait_group %0;\n" :: "n"(n))

// ---------------------------------------------------------------------------
// tf32 GEMM body: C[.,N] tile (brow,bcol) = A[.,K] @ B[K,N] + bias (+res).
// 128x128 tile, K-step 32, 256 threads, 2-stage cp.async pipeline.
// As: (m,k) float4-slot swizzle  kg^(m&7).  Bs: slot (ng&24)|((ng&7)^(2*(k&3)))
// ---------------------------------------------------------------------------
__device__ __forceinline__
void gemm_body(const float* __restrict__ A, const float* __restrict__ Bm,
               const float* __restrict__ bias, const float* __restrict__ res,
               float* __restrict__ C, int N, int K, int brow, int bcol,
               float* As0, float* Bs0, bool addres)
{
    const int tid   = threadIdx.x;
    const int lane  = tid & 31;
    const int warp  = tid >> 5;
    const int g     = lane >> 2;
    const int tg    = lane & 3;
    const int warpM = warp & 3;
    const int warpN = warp >> 2;

    float acc[2][8][4];
#pragma unroll
    for (int mt = 0; mt < 2; mt++)
#pragma unroll
        for (int nt = 0; nt < 8; nt++)
#pragma unroll
            for (int e = 0; e < 4; e++) acc[mt][nt][e] = 0.f;

    // async tile loaders
    const int aM = tid >> 3, aK = (tid & 7);          // not used directly; see loop
    (void)aM; (void)aK;

    auto issue = [&](int kt, int buf) {
        float* Asb = As0 + buf * 4096;
        float* Bsb = Bs0 + buf * 4096;
#pragma unroll
        for (int i = 0; i < 4; i++) {
            int lin = i * 256 + tid;
            int m = lin >> 3, kg = lin & 7;
            const float* src = A + (size_t)(brow + m) * K + kt + kg * 4;
            CPA(su(Asb + m * 32 + ((kg ^ (m & 7)) << 2)), src);
        }
#pragma unroll
        for (int i = 0; i < 4; i++) {
            int lin = i * 256 + tid;
            int k = lin >> 5, ng = lin & 31;
            const float* src = Bm + (size_t)(kt + k) * N + bcol + ng * 4;
            CPA(su(Bsb + k * 128 + (((ng & 24) | ((ng & 7) ^ (2 * (k & 3)))) << 2)), src);
        }
    };

    const int nkt = K >> 5;
    issue(0, 0);
    CPC();

    for (int t = 0; t < nkt; t++) {
        if (t + 1 < nkt) { issue((t + 1) << 5, (t + 1) & 1); CPC(); CPW(1); }
        else             { CPC(); CPW(0); }
        __syncthreads();

        const float* As = As0 + (t & 1) * 4096;
        const float* Bs = Bs0 + (t & 1) * 4096;

#pragma unroll
        for (int k8 = 0; k8 < 4; k8++) {
            const int kk = k8 * 8 + tg;
            unsigned af[2][4], bf[8][2];
#pragma unroll
            for (int mt = 0; mt < 2; mt++) {
                const int r = warpM * 32 + mt * 16 + g;
                const float* r0 = As + r * 32;
                const float* r1 = As + (r + 8) * 32;
                const int s = 4 * g;
                af[mt][0] = __float_as_uint(r0[kk ^ s]);
                af[mt][1] = __float_as_uint(r1[kk ^ s]);
                af[mt][2] = __float_as_uint(r0[(kk + 4) ^ s]);
                af[mt][3] = __float_as_uint(r1[(kk + 4) ^ s]);
            }
#pragma unroll
            for (int nt = 0; nt < 8; nt++) {
                const int c = warpN * 64 + nt * 8 + g;
                const int cs = (c & 96) | ((c & 31) ^ (8 * tg));
                bf[nt][0] = __float_as_uint(Bs[kk * 128 + cs]);
                bf[nt][1] = __float_as_uint(Bs[(kk + 4) * 128 + cs]);
            }
#pragma unroll
            for (int mt = 0; mt < 2; mt++)
#pragma unroll
                for (int nt = 0; nt < 8; nt++)
                    mma_tf32(acc[mt][nt], af[mt], bf[nt]);
        }
        __syncthreads();
    }

#pragma unroll
    for (int mt = 0; mt < 2; mt++) {
        const int r0 = brow + warpM * 32 + mt * 16 + g;
#pragma unroll
        for (int nt = 0; nt < 8; nt++) {
            const int c = bcol + warpN * 64 + nt * 8 + 2 * tg;
            float2 bi = *(const float2*)(bias + c);
            float2 o0, o1;
            o0.x = acc[mt][nt][0] + bi.x;  o0.y = acc[mt][nt][1] + bi.y;
            o1.x = acc[mt][nt][2] + bi.x;  o1.y = acc[mt][nt][3] + bi.y;
            if (addres) {
                float2 ra = *(const float2*)(res + (size_t)r0 * N + c);
                float2 rb = *(const float2*)(res + (size_t)(r0 + 8) * N + c);
                o0.x += ra.x; o0.y += ra.y;
                o1.x += rb.x; o1.y += rb.y;
            }
            *(float2*)(C + (size_t)r0 * N + c)       = o0;
            *(float2*)(C + (size_t)(r0 + 8) * N + c) = o1;
        }
    }
}

// Fused Q/K/V projection: grid (24, 32); bx>>3 selects which projection.
__global__ __launch_bounds__(256, 2)
void qkv_tc(const float* __restrict__ x,
            const float* __restrict__ Wq, const float* __restrict__ bq,
            const float* __restrict__ Wk, const float* __restrict__ bk,
            const float* __restrict__ Wv, const float* __restrict__ bv,
            float* __restrict__ q, float* __restrict__ k, float* __restrict__ v)
{
    extern __shared__ float smem[];
    const int which = blockIdx.x >> 3;
    const float* W  = (which == 0) ? Wq : (which == 1) ? Wk : Wv;
    const float* bi = (which == 0) ? bq : (which == 1) ? bk : bv;
    float* out      = (which == 0) ? q  : (which == 1) ? k  : v;
    gemm_body(x, W, bi, nullptr, out, DD, DD,
              blockIdx.y * 128, (blockIdx.x & 7) * 128, smem, smem + 8192, false);
}

// Output projection + residual.
__global__ __launch_bounds__(256, 2)
void out_tc(const float* __restrict__ A, const float* __restrict__ W,
            const float* __restrict__ bias, const float* __restrict__ res,
            float* __restrict__ C)
{
    extern __shared__ float smem[];
    gemm_body(A, W, bias, res, C, DD, DD,
              blockIdx.y * 128, blockIdx.x * 128, smem, smem + 8192, true);
}

// ---------------------------------------------------------------------------
// Flash attention, tf32 tensor cores. Block = (b,h,128-query tile),
// 128 threads = 4 warps, each warp owns 32 q-rows (2 m16 tiles) so K/V
// fragments are reused across 2 mma's. K/V tiles (64 kv rows) double-buffered
// via cp.async. P goes through smem to reach A-fragment layout.
// ---------------------------------------------------------------------------
__global__ __launch_bounds__(128, 2)
void flash_tc(const float* __restrict__ Q, const float* __restrict__ Kg,
              const float* __restrict__ Vg, float* __restrict__ O)
{
    extern __shared__ float smem[];
    float* KsA = smem;            // [2][64*64]
    float* VsA = smem + 8192;     // [2][64*64]
    float* Ps  = smem + 16384;    // [128*64]  (also Q staging)

    const int qt   = (int)gridDim.x - 1 - (int)blockIdx.x;  // big tiles first
    const int h    = blockIdx.y, b = blockIdx.z;
    const int tid  = threadIdx.x;
    const int w    = tid >> 5;
    const int lane = tid & 31;
    const int g    = lane >> 2;
    const int tg   = lane & 3;
    const int sw   = 4 * g;
    const size_t base = ((size_t)(b * HH + h)) * SS * DKH;

    auto issueKV = [&](int kt, int buf) {
        float* Kb = KsA + buf * 4096;
        float* Vb = VsA + buf * 4096;
        const float* gk = Kg + base + (size_t)kt * 64 * DKH;
        const float* gv = Vg + base + (size_t)kt * 64 * DKH;
#pragma unroll
        for (int i = 0; i < 8; i++) {
            int lin = i * 128 + tid;
            int j = lin >> 4, dg = lin & 15;
            CPA(su(Kb + j * 64 + ((dg ^ (j & 7)) << 2)),       gk + j * 64 + dg * 4);
            CPA(su(Vb + j * 64 + ((dg ^ (2 * (j & 3))) << 2)), gv + j * 64 + dg * 4);
        }
    };

    issueKV(0, 0);
    CPC();

    // stage Q (scaled by 1/8) into Ps, then pull fragments for both m-tiles
    {
        const float* gq = Q + base + (size_t)qt * 128 * DKH;
#pragma unroll
        for (int i = 0; i < 16; i++) {
            int lin = i * 128 + tid;
            int r = lin >> 4, dg = lin & 15;
            float4 t = *(const float4*)(gq + r * 64 + dg * 4);
            t.x *= 0.125f; t.y *= 0.125f; t.z *= 0.125f; t.w *= 0.125f;
            *(float4*)(Ps + r * 64 + ((dg ^ (r & 7)) << 2)) = t;
        }
    }
    __syncthreads();

    unsigned qf[2][8][4];
#pragma unroll
    for (int mt = 0; mt < 2; mt++) {
        const int r = w * 32 + mt * 16 + g;
        const float* p0 = Ps + r * 64;
        const float* p1 = Ps + (r + 8) * 64;
#pragma unroll
        for (int k8 = 0; k8 < 8; k8++) {
            const int kk = k8 * 8 + tg;
            qf[mt][k8][0] = __float_as_uint(p0[kk ^ sw]);
            qf[mt][k8][1] = __float_as_uint(p1[kk ^ sw]);
            qf[mt][k8][2] = __float_as_uint(p0[(kk + 4) ^ sw]);
            qf[mt][k8][3] = __float_as_uint(p1[(kk + 4) ^ sw]);
        }
    }
    __syncthreads();   // Ps now free for P

    float oacc[2][8][4];
#pragma unroll
    for (int mt = 0; mt < 2; mt++)
#pragma unroll
        for (int nt = 0; nt < 8; nt++)
#pragma unroll
            for (int e = 0; e < 4; e++) oacc[mt][nt][e] = 0.f;
    float mrow[4] = {-1e30f, -1e30f, -1e30f, -1e30f};
    float lrow[4] = {0.f, 0.f, 0.f, 0.f};

    const int nkt = 2 * qt + 2;
    for (int kt = 0; kt < nkt; kt++) {
        if (kt + 1 < nkt) { issueKV(kt + 1, (kt + 1) & 1); CPC(); CPW(1); }
        else              { CPC(); CPW(0); }
        __syncthreads();

        const float* Ks = KsA + (kt & 1) * 4096;
        const float* Vs = VsA + (kt & 1) * 4096;

        // ---- S = Q @ K^T (K fragments shared across both m-tiles) ----
        float sacc[2][8][4];
#pragma unroll
        for (int mt = 0; mt < 2; mt++)
#pragma unroll
            for (int nt = 0; nt < 8; nt++)
#pragma unroll
                for (int e = 0; e < 4; e++) sacc[mt][nt][e] = 0.f;

#pragma unroll
        for (int k8 = 0; k8 < 8; k8++) {
            const int kk = k8 * 8 + tg;
#pragma unroll
            for (int nt = 0; nt < 8; nt++) {
                const int j = nt * 8 + g;
                unsigned bf[2];
                bf[0] = __float_as_uint(Ks[j * 64 + (kk ^ sw)]);
                bf[1] = __float_as_uint(Ks[j * 64 + ((kk + 4) ^ sw)]);
                mma_tf32(sacc[0][nt], qf[0][k8], bf);
                mma_tf32(sacc[1][nt], qf[1][k8], bf);
            }
        }

        // ---- causal mask ----
        const int rowbase = qt * 128 + w * 32;
        const int colbase = kt * 64;
        if (colbase + 63 > rowbase) {
#pragma unroll
            for (int mt = 0; mt < 2; mt++) {
                const int rA = rowbase + mt * 16 + g;
                const int rB = rA + 8;
#pragma unroll
                for (int nt = 0; nt < 8; nt++) {
                    const int c = colbase + nt * 8 + 2 * tg;
                    if (c     > rA) sacc[mt][nt][0] = -1e30f;
                    if (c + 1 > rA) sacc[mt][nt][1] = -1e30f;
                    if (c     > rB) sacc[mt][nt][2] = -1e30f;
                    if (c + 1 > rB) sacc[mt][nt][3] = -1e30f;
                }
            }
        }

        // ---- online softmax + P write ----
#pragma unroll
        for (int mt = 0; mt < 2; mt++) {
            float t0 = -1e30f, t1 = -1e30f;
#pragma unroll
            for (int nt = 0; nt < 8; nt++) {
                t0 = fmaxf(t0, fmaxf(sacc[mt][nt][0], sacc[mt][nt][1]));
                t1 = fmaxf(t1, fmaxf(sacc[mt][nt][2], sacc[mt][nt][3]));
            }
            t0 = fmaxf(t0, __shfl_xor_sync(0xffffffffu, t0, 1));
            t0 = fmaxf(t0, __shfl_xor_sync(0xffffffffu, t0, 2));
            t1 = fmaxf(t1, __shfl_xor_sync(0xffffffffu, t1, 1));
            t1 = fmaxf(t1, __shfl_xor_sync(0xffffffffu, t1, 2));

            const float mn0 = fmaxf(mrow[2 * mt], t0);
            const float mn1 = fmaxf(mrow[2 * mt + 1], t1);
            const float c0  = __expf(mrow[2 * mt] - mn0);
            const float c1  = __expf(mrow[2 * mt + 1] - mn1);
            mrow[2 * mt] = mn0; mrow[2 * mt + 1] = mn1;
            lrow[2 * mt] *= c0; lrow[2 * mt + 1] *= c1;
#pragma unroll
            for (int nt = 0; nt < 8; nt++) {
                oacc[mt][nt][0] *= c0; oacc[mt][nt][1] *= c0;
                oacc[mt][nt][2] *= c1; oacc[mt][nt][3] *= c1;
            }
            float s0 = 0.f, s1 = 0.f;
#pragma unroll
            for (int nt = 0; nt < 8; nt++) {
                sacc[mt][nt][0] = __expf(sacc[mt][nt][0] - mn0);
                sacc[mt][nt][1] = __expf(sacc[mt][nt][1] - mn0);
                sacc[mt][nt][2] = __expf(sacc[mt][nt][2] - mn1);
                sacc[mt][nt][3] = __expf(sacc[mt][nt][3] - mn1);
                s0 += sacc[mt][nt][0] + sacc[mt][nt][1];
                s1 += sacc[mt][nt][2] + sacc[mt][nt][3];
            }
            s0 += __shfl_xor_sync(0xffffffffu, s0, 1);
            s0 += __shfl_xor_sync(0xffffffffu, s0, 2);
            s1 += __shfl_xor_sync(0xffffffffu, s1, 1);
            s1 += __shfl_xor_sync(0xffffffffu, s1, 2);
            lrow[2 * mt] += s0; lrow[2 * mt + 1] += s1;

            const int rA = w * 32 + mt * 16 + g;
#pragma unroll
            for (int nt = 0; nt < 8; nt++) {
                const int c = (nt * 8 + 2 * tg) ^ sw;
                float2 pa, pb;
                pa.x = sacc[mt][nt][0]; pa.y = sacc[mt][nt][1];
                pb.x = sacc[mt][nt][2]; pb.y = sacc[mt][nt][3];
                *(float2*)(Ps + rA * 64 + c)       = pa;
                *(float2*)(Ps + (rA + 8) * 64 + c) = pb;
            }
        }
        __syncwarp();

        // ---- O += P @ V (V fragments shared across both m-tiles) ----
#pragma unroll
        for (int k8 = 0; k8 < 8; k8++) {
            const int kk = k8 * 8 + tg;
            unsigned vf[8][2];
#pragma unroll
            for (int nt = 0; nt < 8; nt++) {
                const int d = nt * 8 + g;
                vf[nt][0] = __float_as_uint(Vs[kk * 64 + (d ^ (8 * tg))]);
                vf[nt][1] = __float_as_uint(Vs[(kk + 4) * 64 + (d ^ (8 * tg))]);
            }
#pragma unroll
            for (int mt = 0; mt < 2; mt++) {
                const int rA = w * 32 + mt * 16 + g;
                const float* pr0 = Ps + rA * 64;
                const float* pr1 = Ps + (rA + 8) * 64;
                unsigned pa[4];
                pa[0] = __float_as_uint(pr0[kk ^ sw]);
                pa[1] = __float_as_uint(pr1[kk ^ sw]);
                pa[2] = __float_as_uint(pr0[(kk + 4) ^ sw]);
                pa[3] = __float_as_uint(pr1[(kk + 4) ^ sw]);
#pragma unroll
                for (int nt = 0; nt < 8; nt++)
                    mma_tf32(oacc[mt][nt], pa, vf[nt]);
            }
        }
        __syncthreads();
    }

    // ---- epilogue ----
#pragma unroll
    for (int mt = 0; mt < 2; mt++) {
        const float i0 = 1.0f / lrow[2 * mt];
        const float i1 = 1.0f / lrow[2 * mt + 1];
        const int rg = qt * 128 + w * 32 + mt * 16 + g;
#pragma unroll
        for (int nt = 0; nt < 8; nt++) {
            const int c = nt * 8 + 2 * tg;
            float2 o0, o1;
            o0.x = oacc[mt][nt][0] * i0; o0.y = oacc[mt][nt][1] * i0;
            o1.x = oacc[mt][nt][2] * i1; o1.y = oacc[mt][nt][3] * i1;
            *(float2*)(O + base + (size_t)rg * DKH + c)       = o0;
            *(float2*)(O + base + (size_t)(rg + 8) * DKH + c) = o1;
        }
    }
}

// ---------------------------------------------------------------------------
// LayerNorm over rows of 1024.
// ---------------------------------------------------------------------------
__global__ __launch_bounds__(256)
void ln_kernel(const float* __restrict__ in, const float* __restrict__ gamma,
               const float* __restrict__ beta, float* __restrict__ out)
{
    const int row = blockIdx.x;
    const int t   = threadIdx.x;
    const float4* r = (const float4*)(in + (size_t)row * DD);
    float4 v = r[t];

    float s  = v.x + v.y + v.z + v.w;
    float s2 = v.x * v.x + v.y * v.y + v.z * v.z + v.w * v.w;

#pragma unroll
    for (int off = 16; off > 0; off >>= 1) {
        s  += __shfl_xor_sync(0xffffffffu, s,  off);
        s2 += __shfl_xor_sync(0xffffffffu, s2, off);
    }
    __shared__ float sm[8], sm2[8];
    const int warp = t >> 5, lane = t & 31;
    if (lane == 0) { sm[warp] = s; sm2[warp] = s2; }
    __syncthreads();
    float tot = 0.f, tot2 = 0.f;
#pragma unroll
    for (int w = 0; w < 8; w++) { tot += sm[w]; tot2 += sm2[w]; }

    const float mean = tot * (1.0f / DD);
    const float var  = tot2 * (1.0f / DD) - mean * mean;
    const float rstd = rsqrtf(var + 1e-5f);

    float4 g  = ((const float4*)gamma)[t];
    float4 be = ((const float4*)beta)[t];
    float4 o;
    o.x = (v.x - mean) * rstd * g.x + be.x;
    o.y = (v.y - mean) * rstd * g.y + be.y;
    o.z = (v.z - mean) * rstd * g.z + be.z;
    o.w = (v.w - mean) * rstd * g.w + be.w;
    ((float4*)(out + (size_t)row * DD))[t] = o;
}

// ---------------------------------------------------------------------------
extern "C" void kernel_launch(void* const* d_in, const int* in_sizes, int n_in,
                              void* d_out, int out_size)
{
    const float* x     = (const float*)d_in[0];
    const float* Wk    = (const float*)d_in[1];
    const float* bk    = (const float*)d_in[2];
    const float* Wq    = (const float*)d_in[3];
    const float* bq    = (const float*)d_in[4];
    const float* Wv    = (const float*)d_in[5];
    const float* bv    = (const float*)d_in[6];
    const float* Wo    = (const float*)d_in[7];
    const float* bo    = (const float*)d_in[8];
    const float* gamma = (const float*)d_in[9];
    const float* beta  = (const float*)d_in[10];
    float* out = (float*)d_out;

    float *q, *k, *v, *ctx, *o;
    cudaGetSymbolAddress((void**)&q,   g_q);
    cudaGetSymbolAddress((void**)&k,   g_k);
    cudaGetSymbolAddress((void**)&v,   g_v);
    cudaGetSymbolAddress((void**)&ctx, g_ctx);
    cudaGetSymbolAddress((void**)&o,   g_o);

    const int gemm_smem  = 2 * (4096 + 4096) * sizeof(float);   // 64 KB
    const int flash_smem = (8192 + 8192 + 8192) * sizeof(float); // 96 KB
    cudaFuncSetAttribute(qkv_tc,   cudaFuncAttributeMaxDynamicSharedMemorySize, gemm_smem);
    cudaFuncSetAttribute(out_tc,   cudaFuncAttributeMaxDynamicSharedMemorySize, gemm_smem);
    cudaFuncSetAttribute(flash_tc, cudaFuncAttributeMaxDynamicSharedMemorySize, flash_smem);

    qkv_tc<<<dim3(24, 32), 256, gemm_smem>>>(x, Wq, bq, Wk, bk, Wv, bv, q, k, v);

    flash_tc<<<dim3(SS / 128, HH, BB), 128, flash_smem>>>(q, k, v, ctx);

    out_tc<<<dim3(8, 32), 256, gemm_smem>>>(ctx, Wo, bo, x, o);

    ln_kernel<<<MTOK, 256>>>(o, gamma, beta, out);
}

// round 4
// speedup vs baseline: 8.6767x; 1.8293x over previous
#include <cuda_runtime.h>
#include <cuda_bf16.h>
#include <cstdint>

#define BB   2
#define SS   2048
#define DD   1024
#define HH   16
#define DKH  64
#define MTOK (BB*SS)
#define ELEMS (BB*SS*DD)

// bf16 staging buffers + f32 pre-LN buffer
__device__ __nv_bfloat16 g_xb[ELEMS];
__device__ __nv_bfloat16 g_wqb[DD*DD];
__device__ __nv_bfloat16 g_wkb[DD*DD];
__device__ __nv_bfloat16 g_wvb[DD*DD];
__device__ __nv_bfloat16 g_wob[DD*DD];
__device__ __nv_bfloat16 g_qb[ELEMS];
__device__ __nv_bfloat16 g_kb[ELEMS];
__device__ __nv_bfloat16 g_vb[ELEMS];
__device__ __nv_bfloat16 g_ctxb[ELEMS];
__device__ float g_o[ELEMS];

// ---------------------------------------------------------------------------
// helpers
// ---------------------------------------------------------------------------
__device__ __forceinline__ void mma_bf16(float c[4], const unsigned a[4], const unsigned b[2]) {
    asm volatile(
        "mma.sync.aligned.m16n8k16.row.col.f32.bf16.bf16.f32 "
        "{%0,%1,%2,%3}, {%4,%5,%6,%7}, {%8,%9}, {%0,%1,%2,%3};\n"
        : "+f"(c[0]), "+f"(c[1]), "+f"(c[2]), "+f"(c[3])
        : "r"(a[0]), "r"(a[1]), "r"(a[2]), "r"(a[3]), "r"(b[0]), "r"(b[1]));
}
__device__ __forceinline__ void ldsm4(unsigned r[4], unsigned addr) {
    asm volatile("ldmatrix.sync.aligned.m8n8.x4.shared.b16 {%0,%1,%2,%3}, [%4];"
        : "=r"(r[0]), "=r"(r[1]), "=r"(r[2]), "=r"(r[3]) : "r"(addr));
}
__device__ __forceinline__ void ldsm4t(unsigned r[4], unsigned addr) {
    asm volatile("ldmatrix.sync.aligned.m8n8.x4.trans.shared.b16 {%0,%1,%2,%3}, [%4];"
        : "=r"(r[0]), "=r"(r[1]), "=r"(r[2]), "=r"(r[3]) : "r"(addr));
}
__device__ __forceinline__ unsigned su(const void* p) {
    return (unsigned)__cvta_generic_to_shared(p);
}
#define CPA(dst, src) asm volatile("cp.async.ca.shared.global [%0], [%1], 16;\n" :: "r"(dst), "l"(src))
#define CPC() asm volatile("cp.async.commit_group;\n")
#define CPW(n) asm volatile("cp.async.wait_group %0;\n" :: "n"(n))

__device__ __forceinline__ unsigned pack_bf(float lo, float hi) {
    __nv_bfloat162 t = __floats2bfloat162_rn(lo, hi);
    return *(unsigned*)&t;
}

// ---------------------------------------------------------------------------
// f32 -> bf16 pre-convert (x + 4 weight matrices), one float4 per thread.
// ---------------------------------------------------------------------------
__global__ __launch_bounds__(256)
void cvt_all(const float* __restrict__ x,
             const float* __restrict__ Wq, const float* __restrict__ Wk,
             const float* __restrict__ Wv, const float* __restrict__ Wo)
{
    int idx = blockIdx.x * 256 + threadIdx.x;       // float4 index
    const float* src; __nv_bfloat16* dst; int j;
    if (idx < 1048576) { src = x; dst = g_xb; j = idx; }
    else {
        int t = idx - 1048576;
        int w = t >> 18;                            // 262144 float4 per W
        j = t & 262143;
        src = (w == 0) ? Wq : (w == 1) ? Wk : (w == 2) ? Wv : Wo;
        dst = (w == 0) ? g_wqb : (w == 1) ? g_wkb : (w == 2) ? g_wvb : g_wob;
    }
    float4 v = ((const float4*)src)[j];
    uint2 u;
    u.x = pack_bf(v.x, v.y);
    u.y = pack_bf(v.z, v.w);
    ((uint2*)dst)[j] = u;
}

// ---------------------------------------------------------------------------
// bf16 GEMM body: 128x128 tile, K-step 32, 256 threads, 2-stage cp.async.
// As (m,k): 64B rows, granule swizzle gk^((m>>1)&3).
// Bs (k,n): 256B rows, granule swizzle gn^(k&7). Fragments via ldmatrix.
// ---------------------------------------------------------------------------
template <bool RES, bool OUTBF>
__device__ __forceinline__
void gemm_body(const __nv_bfloat16* __restrict__ A, const __nv_bfloat16* __restrict__ Bm,
               const float* __restrict__ bias, const float* __restrict__ res,
               void* __restrict__ Cout, int N, int K, int brow, int bcol,
               char* smem, float oscale)
{
    const int tid   = threadIdx.x;
    const int lane  = tid & 31;
    const int warp  = tid >> 5;
    const int g     = lane >> 2;
    const int tg    = lane & 3;
    const int warpM = warp & 3;
    const int warpN = warp >> 2;

    const unsigned sA = su(smem);          // 2 x 8KB
    const unsigned sB = sA + 16384;        // 2 x 8KB

    float acc[2][8][4];
#pragma unroll
    for (int mt = 0; mt < 2; mt++)
#pragma unroll
        for (int nt = 0; nt < 8; nt++)
#pragma unroll
            for (int e = 0; e < 4; e++) acc[mt][nt][e] = 0.f;

    auto issue = [&](int kt, int buf) {
        const unsigned ab = sA + buf * 8192;
        const unsigned bb = sB + buf * 8192;
#pragma unroll
        for (int i = 0; i < 2; i++) {
            int lin = i * 256 + tid;
            int m = lin >> 2, gk = lin & 3;
            CPA(ab + m * 64 + 16 * (gk ^ ((m >> 1) & 3)),
                A + (size_t)(brow + m) * K + kt + gk * 8);
        }
#pragma unroll
        for (int i = 0; i < 2; i++) {
            int lin = i * 256 + tid;
            int k = lin >> 4, gn = lin & 15;
            CPA(bb + k * 256 + 16 * (gn ^ (k & 7)),
                Bm + (size_t)(kt + k) * N + bcol + gn * 8);
        }
    };

    const int nkt = K >> 5;
    issue(0, 0);
    CPC();

    for (int t = 0; t < nkt; t++) {
        if (t + 1 < nkt) { issue((t + 1) << 5, (t + 1) & 1); CPC(); CPW(1); }
        else             { CPW(0); }
        __syncthreads();

        const unsigned As = sA + (t & 1) * 8192;
        const unsigned Bs = sB + (t & 1) * 8192;

#pragma unroll
        for (int kk = 0; kk < 32; kk += 16) {
            unsigned af[2][4], bf[8][2];
#pragma unroll
            for (int mt = 0; mt < 2; mt++) {
                int m  = warpM * 32 + mt * 16 + (lane & 7) + (lane & 8);
                int gk = (kk >> 3) + (lane >> 4);
                ldsm4(af[mt], As + m * 64 + 16 * (gk ^ ((m >> 1) & 3)));
            }
#pragma unroll
            for (int n16 = 0; n16 < 4; n16++) {
                int k  = kk + (lane & 7) + (lane & 8);
                int gn = warpN * 8 + n16 * 2 + (lane >> 4);
                unsigned r[4];
                ldsm4t(r, Bs + k * 256 + 16 * (gn ^ (k & 7)));
                bf[2 * n16][0] = r[0];  bf[2 * n16][1] = r[1];
                bf[2 * n16 + 1][0] = r[2];  bf[2 * n16 + 1][1] = r[3];
            }
#pragma unroll
            for (int mt = 0; mt < 2; mt++)
#pragma unroll
                for (int nt = 0; nt < 8; nt++)
                    mma_bf16(acc[mt][nt], af[mt], bf[nt]);
        }
        __syncthreads();
    }

#pragma unroll
    for (int mt = 0; mt < 2; mt++) {
        const int r0 = brow + warpM * 32 + mt * 16 + g;
#pragma unroll
        for (int nt = 0; nt < 8; nt++) {
            const int c = bcol + warpN * 64 + nt * 8 + 2 * tg;
            float2 bi = *(const float2*)(bias + c);
            float o0x = (acc[mt][nt][0] + bi.x) * oscale;
            float o0y = (acc[mt][nt][1] + bi.y) * oscale;
            float o1x = (acc[mt][nt][2] + bi.x) * oscale;
            float o1y = (acc[mt][nt][3] + bi.y) * oscale;
            if (OUTBF) {
                __nv_bfloat16* Cb = (__nv_bfloat16*)Cout;
                unsigned p0 = pack_bf(o0x, o0y);
                unsigned p1 = pack_bf(o1x, o1y);
                *(unsigned*)(Cb + (size_t)r0 * N + c)       = p0;
                *(unsigned*)(Cb + (size_t)(r0 + 8) * N + c) = p1;
            } else {
                float* Cf = (float*)Cout;
                if (RES) {
                    float2 ra = *(const float2*)(res + (size_t)r0 * N + c);
                    float2 rb = *(const float2*)(res + (size_t)(r0 + 8) * N + c);
                    o0x += ra.x; o0y += ra.y;
                    o1x += rb.x; o1y += rb.y;
                }
                float2 w0; w0.x = o0x; w0.y = o0y;
                float2 w1; w1.x = o1x; w1.y = o1y;
                *(float2*)(Cf + (size_t)r0 * N + c)       = w0;
                *(float2*)(Cf + (size_t)(r0 + 8) * N + c) = w1;
            }
        }
    }
}

// Fused Q/K/V projection (q pre-scaled by 1/sqrt(dk)); bf16 outputs.
__global__ __launch_bounds__(256, 2)
void qkv_tc(const __nv_bfloat16* __restrict__ xb,
            const float* __restrict__ bq, const float* __restrict__ bk,
            const float* __restrict__ bv)
{
    extern __shared__ char smem[];
    const int which = blockIdx.x >> 3;
    const __nv_bfloat16* W = (which == 0) ? g_wqb : (which == 1) ? g_wkb : g_wvb;
    const float* bi        = (which == 0) ? bq    : (which == 1) ? bk    : bv;
    __nv_bfloat16* out     = (which == 0) ? g_qb  : (which == 1) ? g_kb  : g_vb;
    const float oscale     = (which == 0) ? 0.125f : 1.0f;
    gemm_body<false, true>(xb, W, bi, nullptr, out, DD, DD,
                           blockIdx.y * 128, (blockIdx.x & 7) * 128, smem, oscale);
}

// Output projection + residual (f32 out).
__global__ __launch_bounds__(256, 2)
void out_tc(const float* __restrict__ bo, const float* __restrict__ x)
{
    extern __shared__ char smem[];
    gemm_body<true, false>(g_ctxb, g_wob, bo, x, g_o, DD, DD,
                           blockIdx.y * 128, blockIdx.x * 128, smem, 1.0f);
}

// ---------------------------------------------------------------------------
// Flash attention, bf16 mma. Block = (b,h,128-row q tile), 4 warps.
// K tile consumed via ldmatrix (col-layout B), V via ldmatrix.trans,
// P through smem (reuses Q staging buffer). K/V double-buffered cp.async.
// ---------------------------------------------------------------------------
__global__ __launch_bounds__(128, 2)
void flash_tc(float* dummy)
{
    extern __shared__ char smem[];
    const unsigned sK = su(smem);          // 2 x 8KB
    const unsigned sV = sK + 16384;        // 2 x 8KB
    const unsigned sP = sV + 16384;        // 16KB (Q staging, then P)

    const int qt   = (int)gridDim.x - 1 - (int)blockIdx.x;
    const int h    = blockIdx.y, b = blockIdx.z;
    const int tid  = threadIdx.x;
    const int w    = tid >> 5;
    const int lane = tid & 31;
    const int g    = lane >> 2;
    const int tg   = lane & 3;
    const size_t base = ((size_t)(b * HH + h)) * SS * DKH;

    // ---- stage Q (already scaled) ----
    {
        const __nv_bfloat16* gq = g_qb + base + (size_t)qt * 128 * DKH;
#pragma unroll
        for (int i = 0; i < 8; i++) {
            int lin = i * 128 + tid;
            int m = lin >> 3, gd = lin & 7;
            CPA(sP + m * 128 + 16 * (gd ^ (m & 7)), gq + m * 64 + gd * 8);
        }
    }
    CPC();

    auto issueKV = [&](int kt, int buf) {
        const unsigned kb = sK + buf * 8192;
        const unsigned vb = sV + buf * 8192;
        const __nv_bfloat16* gk = g_kb + base + (size_t)kt * 64 * DKH;
        const __nv_bfloat16* gv = g_vb + base + (size_t)kt * 64 * DKH;
#pragma unroll
        for (int i = 0; i < 4; i++) {
            int lin = i * 128 + tid;
            int j = lin >> 3, gd = lin & 7;
            const unsigned off = j * 128 + 16 * (gd ^ (j & 7));
            CPA(kb + off, gk + j * 64 + gd * 8);
            CPA(vb + off, gv + j * 64 + gd * 8);
        }
    };

    issueKV(0, 0);
    CPC();
    CPW(1);              // Q group done
    __syncthreads();

    // ---- Q fragments to registers ----
    unsigned qf[2][4][4];
#pragma unroll
    for (int mt = 0; mt < 2; mt++) {
        int m = w * 32 + mt * 16 + (lane & 7) + (lane & 8);
#pragma unroll
        for (int dk = 0; dk < 4; dk++) {
            int gd = dk * 2 + (lane >> 4);
            ldsm4(qf[mt][dk], sP + m * 128 + 16 * (gd ^ (m & 7)));
        }
    }
    __syncthreads();     // sP now free for P

    float oacc[2][8][4];
#pragma unroll
    for (int mt = 0; mt < 2; mt++)
#pragma unroll
        for (int nt = 0; nt < 8; nt++)
#pragma unroll
            for (int e = 0; e < 4; e++) oacc[mt][nt][e] = 0.f;
    float mrow[4] = {-1e30f, -1e30f, -1e30f, -1e30f};
    float lrow[4] = {0.f, 0.f, 0.f, 0.f};

    const int nkt = 2 * qt + 2;
    for (int kt = 0; kt < nkt; kt++) {
        if (kt + 1 < nkt) { issueKV(kt + 1, (kt + 1) & 1); CPC(); CPW(1); }
        else              { CPW(0); }
        __syncthreads();

        const unsigned Ks = sK + (kt & 1) * 8192;
        const unsigned Vs = sV + (kt & 1) * 8192;

        // ---- S = Q @ K^T ----
        float sacc[2][8][4];
#pragma unroll
        for (int mt = 0; mt < 2; mt++)
#pragma unroll
            for (int nt = 0; nt < 8; nt++)
#pragma unroll
                for (int e = 0; e < 4; e++) sacc[mt][nt][e] = 0.f;

#pragma unroll
        for (int dk = 0; dk < 4; dk++) {
            unsigned kbf[8][2];
#pragma unroll
            for (int j16 = 0; j16 < 4; j16++) {
                int j  = j16 * 16 + (lane & 7) + ((lane >> 4) << 3);
                int gd = dk * 2 + ((lane >> 3) & 1);
                unsigned r[4];
                ldsm4(r, Ks + j * 128 + 16 * (gd ^ (j & 7)));
                kbf[2 * j16][0] = r[0];  kbf[2 * j16][1] = r[1];
                kbf[2 * j16 + 1][0] = r[2];  kbf[2 * j16 + 1][1] = r[3];
            }
#pragma unroll
            for (int nt = 0; nt < 8; nt++) {
                mma_bf16(sacc[0][nt], qf[0][dk], kbf[nt]);
                mma_bf16(sacc[1][nt], qf[1][dk], kbf[nt]);
            }
        }

        // ---- causal mask ----
        const int rowbase = qt * 128 + w * 32;
        const int colbase = kt * 64;
        if (colbase + 63 > rowbase) {
#pragma unroll
            for (int mt = 0; mt < 2; mt++) {
                const int rA = rowbase + mt * 16 + g;
                const int rB = rA + 8;
#pragma unroll
                for (int nt = 0; nt < 8; nt++) {
                    const int c = colbase + nt * 8 + 2 * tg;
                    if (c     > rA) sacc[mt][nt][0] = -1e30f;
                    if (c + 1 > rA) sacc[mt][nt][1] = -1e30f;
                    if (c     > rB) sacc[mt][nt][2] = -1e30f;
                    if (c + 1 > rB) sacc[mt][nt][3] = -1e30f;
                }
            }
        }

        // ---- online softmax + P (bf16) ----
#pragma unroll
        for (int mt = 0; mt < 2; mt++) {
            float t0 = -1e30f, t1 = -1e30f;
#pragma unroll
            for (int nt = 0; nt < 8; nt++) {
                t0 = fmaxf(t0, fmaxf(sacc[mt][nt][0], sacc[mt][nt][1]));
                t1 = fmaxf(t1, fmaxf(sacc[mt][nt][2], sacc[mt][nt][3]));
            }
            t0 = fmaxf(t0, __shfl_xor_sync(0xffffffffu, t0, 1));
            t0 = fmaxf(t0, __shfl_xor_sync(0xffffffffu, t0, 2));
            t1 = fmaxf(t1, __shfl_xor_sync(0xffffffffu, t1, 1));
            t1 = fmaxf(t1, __shfl_xor_sync(0xffffffffu, t1, 2));

            const float mn0 = fmaxf(mrow[2 * mt], t0);
            const float mn1 = fmaxf(mrow[2 * mt + 1], t1);
            const float c0  = __expf(mrow[2 * mt] - mn0);
            const float c1  = __expf(mrow[2 * mt + 1] - mn1);
            mrow[2 * mt] = mn0; mrow[2 * mt + 1] = mn1;
            lrow[2 * mt] *= c0; lrow[2 * mt + 1] *= c1;
#pragma unroll
            for (int nt = 0; nt < 8; nt++) {
                oacc[mt][nt][0] *= c0; oacc[mt][nt][1] *= c0;
                oacc[mt][nt][2] *= c1; oacc[mt][nt][3] *= c1;
            }
            float s0 = 0.f, s1 = 0.f;
#pragma unroll
            for (int nt = 0; nt < 8; nt++) {
                sacc[mt][nt][0] = __expf(sacc[mt][nt][0] - mn0);
                sacc[mt][nt][1] = __expf(sacc[mt][nt][1] - mn0);
                sacc[mt][nt][2] = __expf(sacc[mt][nt][2] - mn1);
                sacc[mt][nt][3] = __expf(sacc[mt][nt][3] - mn1);
                s0 += sacc[mt][nt][0] + sacc[mt][nt][1];
                s1 += sacc[mt][nt][2] + sacc[mt][nt][3];
            }
            s0 += __shfl_xor_sync(0xffffffffu, s0, 1);
            s0 += __shfl_xor_sync(0xffffffffu, s0, 2);
            s1 += __shfl_xor_sync(0xffffffffu, s1, 1);
            s1 += __shfl_xor_sync(0xffffffffu, s1, 2);
            lrow[2 * mt] += s0; lrow[2 * mt + 1] += s1;

            const int rA = w * 32 + mt * 16 + g;
            const int rB = rA + 8;
#pragma unroll
            for (int nt = 0; nt < 8; nt++) {
                unsigned p0 = pack_bf(sacc[mt][nt][0], sacc[mt][nt][1]);
                unsigned p1 = pack_bf(sacc[mt][nt][2], sacc[mt][nt][3]);
                asm volatile("st.shared.b32 [%0], %1;\n" ::
                    "r"(sP + rA * 128 + 16 * (nt ^ (rA & 7)) + 4 * tg), "r"(p0));
                asm volatile("st.shared.b32 [%0], %1;\n" ::
                    "r"(sP + rB * 128 + 16 * (nt ^ (rB & 7)) + 4 * tg), "r"(p1));
            }
        }
        __syncwarp();

        // ---- O += P @ V ----
#pragma unroll
        for (int j16 = 0; j16 < 4; j16++) {
            unsigned pf[2][4], vbf[8][2];
#pragma unroll
            for (int mt = 0; mt < 2; mt++) {
                int m  = w * 32 + mt * 16 + (lane & 7) + (lane & 8);
                int gj = j16 * 2 + (lane >> 4);
                ldsm4(pf[mt], sP + m * 128 + 16 * (gj ^ (m & 7)));
            }
#pragma unroll
            for (int d16 = 0; d16 < 4; d16++) {
                int j  = j16 * 16 + (lane & 7) + (lane & 8);
                int gd = d16 * 2 + (lane >> 4);
                unsigned r[4];
                ldsm4t(r, Vs + j * 128 + 16 * (gd ^ (j & 7)));
                vbf[2 * d16][0] = r[0];  vbf[2 * d16][1] = r[1];
                vbf[2 * d16 + 1][0] = r[2];  vbf[2 * d16 + 1][1] = r[3];
            }
#pragma unroll
            for (int mt = 0; mt < 2; mt++)
#pragma unroll
                for (int nt = 0; nt < 8; nt++)
                    mma_bf16(oacc[mt][nt], pf[mt], vbf[nt]);
        }
        __syncthreads();
    }

    // ---- epilogue: ctx bf16 ----
#pragma unroll
    for (int mt = 0; mt < 2; mt++) {
        const float i0 = 1.0f / lrow[2 * mt];
        const float i1 = 1.0f / lrow[2 * mt + 1];
        const int rg = qt * 128 + w * 32 + mt * 16 + g;
#pragma unroll
        for (int nt = 0; nt < 8; nt++) {
            const int c = nt * 8 + 2 * tg;
            unsigned p0 = pack_bf(oacc[mt][nt][0] * i0, oacc[mt][nt][1] * i0);
            unsigned p1 = pack_bf(oacc[mt][nt][2] * i1, oacc[mt][nt][3] * i1);
            *(unsigned*)(g_ctxb + base + (size_t)rg * DKH + c)       = p0;
            *(unsigned*)(g_ctxb + base + (size_t)(rg + 8) * DKH + c) = p1;
        }
    }
}

// ---------------------------------------------------------------------------
// LayerNorm over rows of 1024.
// ---------------------------------------------------------------------------
__global__ __launch_bounds__(256)
void ln_kernel(const float* __restrict__ gamma, const float* __restrict__ beta,
               float* __restrict__ out)
{
    const int row = blockIdx.x;
    const int t   = threadIdx.x;
    const float4* r = (const float4*)(g_o + (size_t)row * DD);
    float4 v = r[t];

    float s  = v.x + v.y + v.z + v.w;
    float s2 = v.x * v.x + v.y * v.y + v.z * v.z + v.w * v.w;

#pragma unroll
    for (int off = 16; off > 0; off >>= 1) {
        s  += __shfl_xor_sync(0xffffffffu, s,  off);
        s2 += __shfl_xor_sync(0xffffffffu, s2, off);
    }
    __shared__ float sm[8], sm2[8];
    const int warp = t >> 5, lane = t & 31;
    if (lane == 0) { sm[warp] = s; sm2[warp] = s2; }
    __syncthreads();
    float tot = 0.f, tot2 = 0.f;
#pragma unroll
    for (int w = 0; w < 8; w++) { tot += sm[w]; tot2 += sm2[w]; }

    const float mean = tot * (1.0f / DD);
    const float var  = tot2 * (1.0f / DD) - mean * mean;
    const float rstd = rsqrtf(var + 1e-5f);

    float4 g  = ((const float4*)gamma)[t];
    float4 be = ((const float4*)beta)[t];
    float4 o;
    o.x = (v.x - mean) * rstd * g.x + be.x;
    o.y = (v.y - mean) * rstd * g.y + be.y;
    o.z = (v.z - mean) * rstd * g.z + be.z;
    o.w = (v.w - mean) * rstd * g.w + be.w;
    ((float4*)(out + (size_t)row * DD))[t] = o;
}

// ---------------------------------------------------------------------------
extern "C" void kernel_launch(void* const* d_in, const int* in_sizes, int n_in,
                              void* d_out, int out_size)
{
    const float* x     = (const float*)d_in[0];
    const float* Wk    = (const float*)d_in[1];
    const float* bk    = (const float*)d_in[2];
    const float* Wq    = (const float*)d_in[3];
    const float* bq    = (const float*)d_in[4];
    const float* Wv    = (const float*)d_in[5];
    const float* bv    = (const float*)d_in[6];
    const float* Wo    = (const float*)d_in[7];
    const float* bo    = (const float*)d_in[8];
    const float* gamma = (const float*)d_in[9];
    const float* beta  = (const float*)d_in[10];
    float* out = (float*)d_out;

    __nv_bfloat16* xb;
    cudaGetSymbolAddress((void**)&xb, g_xb);   // (forces symbol resolution)

    const int gemm_smem  = 32768;
    const int flash_smem = 49152;
    cudaFuncSetAttribute(qkv_tc,   cudaFuncAttributeMaxDynamicSharedMemorySize, gemm_smem);
    cudaFuncSetAttribute(out_tc,   cudaFuncAttributeMaxDynamicSharedMemorySize, gemm_smem);
    cudaFuncSetAttribute(flash_tc, cudaFuncAttributeMaxDynamicSharedMemorySize, flash_smem);

    cvt_all<<<8192, 256>>>(x, Wq, Wk, Wv, Wo);

    qkv_tc<<<dim3(24, 32), 256, gemm_smem>>>(xb, bq, bk, bv);

    flash_tc<<<dim3(SS / 128, HH, BB), 128, flash_smem>>>(nullptr);

    out_tc<<<dim3(8, 32), 256, gemm_smem>>>(bo, x);

    ln_kernel<<<MTOK, 256>>>(gamma, beta, out);
}